// round 11
// baseline (speedup 1.0000x reference)
#include <cuda_runtime.h>
#include <cstdint>

#define NJ    55
#define TPB   64               // 2 warps per CTA, 1 vertex per thread
#define VPT   64               // vertices per tile
#define WBUF  (VPT * NJ)       // 3520 floats = 14080 B per buffer
#define GRID  (148 * 7)        // 7 CTAs per SM
#define SMEM_BYTES (2 * WBUF * 4 + NJ * 3 * 16)   // 28160 + 2640 = 30800 B

// Packed f32x2 FMA: d = a*b + d  (Blackwell packed fp32 pipe)
#define FMA_F32X2(acc, a, b) \
    asm("fma.rn.f32x2 %0, %1, %2, %0;" : "+l"(acc) : "l"(a), "l"(b))

__device__ __forceinline__ void cp_async16(uint32_t s, const void* g) {
    asm volatile("cp.async.cg.shared.global [%0], [%1], 16;" :: "r"(s), "l"(g));
}
__device__ __forceinline__ void cp_commit() {
    asm volatile("cp.async.commit_group;");
}
__device__ __forceinline__ void cp_wait1() {
    asm volatile("cp.async.wait_group 1;" ::: "memory");
}

// Stage one 64-vertex tile's weights (coalesced float4 cp.async).
// base = tile*64 -> base*55 words divisible by 4 -> 16B-aligned gmem.
__device__ __forceinline__ void prefetch_tile(const float* __restrict__ weights,
                                              int n, int tile, float* buf, int tid)
{
    int base = tile * VPT;
    int nf = (n - base) * NJ;
    if (nf <= 0) return;
    if (nf > WBUF) nf = WBUF;
    const float* g = weights + (size_t)base * NJ;
    uint32_t s = (uint32_t)__cvta_generic_to_shared(buf);
    int n4 = nf >> 2;                      // 880 for a full tile (exact: 64*55/4)
    for (int i = tid; i < n4; i += TPB)
        cp_async16(s + i * 16, g + i * 4);
}

__global__ void __launch_bounds__(TPB)
lbs_kernel(const float* __restrict__ points,
           const float* __restrict__ weights,
           const float* __restrict__ SE3,
           float* __restrict__ out,
           int n, int ntiles)
{
    extern __shared__ __align__(16) float smem[];
    float*   buf0 = smem;
    float*   buf1 = smem + WBUF;
    double2* sm   = (double2*)(smem + 2 * WBUF);   // SE3 rows 0..2 as packed f32x2 pairs

    const int tid = threadIdx.x;
    const int stride = gridDim.x;

    // --- Stage SE3 once (rows 0..2 of each joint; each row is one float4) ---
    {
        const float4* g = (const float4*)SE3;
        for (int idx = tid; idx < NJ * 3; idx += TPB) {
            int j = idx / 3;
            int r = idx - j * 3;
            float4 v = g[j * 4 + r];
            *(float4*)(&sm[idx]) = v;
        }
    }

    // --- Prologue: fill buf0 with first tile ---
    const int first = blockIdx.x;
    prefetch_tile(weights, n, first, buf0, tid);
    cp_commit();

    int p = 0;
    for (int tile = first; tile < ntiles; tile += stride) {
        // Prefetch next tile into the other buffer (lookahead = 1 tile period).
        // Trailing __syncthreads of the previous iteration guarantees nobody
        // still reads that buffer.
        int next = tile + stride;
        if (next < ntiles) prefetch_tile(weights, n, next, p ? buf0 : buf1, tid);
        cp_commit();   // always commit so wait_group(1) targets this tile's group

        const int v = tile * VPT + tid;
        const bool has = (v < n);

        // Point loads fly while waiting
        float px = 0.f, py = 0.f, pz = 0.f;
        if (has) {
            px = __ldg(&points[(size_t)v * 3 + 0]);
            py = __ldg(&points[(size_t)v * 3 + 1]);
            pz = __ldg(&points[(size_t)v * 3 + 2]);
        }

        cp_wait1();        // this tile's buffer complete (only newest group pending)
        __syncthreads();   // cross-thread visibility (covers SE3 staging on iter 0)

        if (has) {
            // Packed accumulators for the blended 3x4 matrix
            unsigned long long a0 = 0ull, a1 = 0ull, a2 = 0ull,
                               a3 = 0ull, a4 = 0ull, a5 = 0ull;

            const float* wrow = (p ? buf1 : buf0) + tid * NJ;  // stride 55 -> conflict-free

            #pragma unroll
            for (int j = 0; j < NJ; ++j) {
                float w = wrow[j];
                unsigned long long w2;
                asm("mov.b64 %0, {%1, %1};" : "=l"(w2) : "r"(__float_as_uint(w)));

                double2 r0 = sm[j * 3 + 0];   // LDS.128 broadcast
                double2 r1 = sm[j * 3 + 1];
                double2 r2 = sm[j * 3 + 2];

                FMA_F32X2(a0, w2, __double_as_longlong(r0.x));
                FMA_F32X2(a1, w2, __double_as_longlong(r0.y));
                FMA_F32X2(a2, w2, __double_as_longlong(r1.x));
                FMA_F32X2(a3, w2, __double_as_longlong(r1.y));
                FMA_F32X2(a4, w2, __double_as_longlong(r2.x));
                FMA_F32X2(a5, w2, __double_as_longlong(r2.y));
            }

            float A00, A01, A02, A03, A10, A11, A12, A13, A20, A21, A22, A23;
            asm("mov.b64 {%0, %1}, %2;" : "=f"(A00), "=f"(A01) : "l"(a0));
            asm("mov.b64 {%0, %1}, %2;" : "=f"(A02), "=f"(A03) : "l"(a1));
            asm("mov.b64 {%0, %1}, %2;" : "=f"(A10), "=f"(A11) : "l"(a2));
            asm("mov.b64 {%0, %1}, %2;" : "=f"(A12), "=f"(A13) : "l"(a3));
            asm("mov.b64 {%0, %1}, %2;" : "=f"(A20), "=f"(A21) : "l"(a4));
            asm("mov.b64 {%0, %1}, %2;" : "=f"(A22), "=f"(A23) : "l"(a5));

            out[(size_t)v * 3 + 0] = fmaf(A00, px, fmaf(A01, py, fmaf(A02, pz, A03)));
            out[(size_t)v * 3 + 1] = fmaf(A10, px, fmaf(A11, py, fmaf(A12, pz, A13)));
            out[(size_t)v * 3 + 2] = fmaf(A20, px, fmaf(A21, py, fmaf(A22, pz, A23)));
        }

        __syncthreads();   // all warps done reading buf[p] before it is refilled
        p ^= 1;
    }
}

extern "C" void kernel_launch(void* const* d_in, const int* in_sizes, int n_in,
                              void* d_out, int out_size)
{
    const float* points  = (const float*)d_in[0];   // [n,3]
    const float* weights = (const float*)d_in[1];   // [n,55]
    const float* SE3     = (const float*)d_in[2];   // [55,4,4]
    float* out = (float*)d_out;

    int n = in_sizes[0] / 3;
    int ntiles = (n + VPT - 1) / VPT;

    cudaFuncSetAttribute(lbs_kernel, cudaFuncAttributeMaxDynamicSharedMemorySize, SMEM_BYTES);

    int grid = (ntiles < GRID) ? ntiles : GRID;
    lbs_kernel<<<grid, TPB, SMEM_BYTES>>>(points, weights, SE3, out, n, ntiles);
}

// round 13
// speedup vs baseline: 1.2900x; 1.2900x over previous
#include <cuda_runtime.h>
#include <cstdint>

#define NJ    55
#define TPB   64               // threads per block (2 warps)
#define VPB   128              // vertices per tile (2 per thread)
#define WBUF  (VPB * NJ)       // 7040 floats = 28160 B (single buffer)
#define GRID  (148 * 7)        // 7 CTAs per SM; co-resident CTAs differ in bid/148
#define SMEM_BYTES (WBUF * 4 + NJ * 3 * 16)   // 28160 + 2640 = 30800 B
#define STAGGER_NS 300         // per-step startup stagger

// Packed f32x2 FMA: d = a*b + d  (Blackwell packed fp32 pipe)
#define FMA_F32X2(acc, a, b) \
    asm("fma.rn.f32x2 %0, %1, %2, %0;" : "+l"(acc) : "l"(a), "l"(b))

__device__ __forceinline__ void cp_async16(uint32_t s, const void* g) {
    asm volatile("cp.async.cg.shared.global [%0], [%1], 16;" :: "r"(s), "l"(g));
}
__device__ __forceinline__ void cp_async4(uint32_t s, const void* g) {
    asm volatile("cp.async.ca.shared.global [%0], [%1], 4;" :: "r"(s), "l"(g));
}
__device__ __forceinline__ void cp_commit() {
    asm volatile("cp.async.commit_group;");
}
__device__ __forceinline__ void cp_wait0() {
    asm volatile("cp.async.wait_group 0;" ::: "memory");
}

__device__ __forceinline__ void prefetch_tile(const float* __restrict__ weights,
                                              int n, int tile, float* swbuf, int tid)
{
    int base = tile * VPB;
    int nf = (n - base) * NJ;
    if (nf > WBUF) nf = WBUF;
    const float* g = weights + (size_t)base * NJ;   // base % 4 == 0 -> 16B aligned
    uint32_t sbase = (uint32_t)__cvta_generic_to_shared(swbuf);
    int n4 = nf >> 2;
    for (int i = tid; i < n4; i += TPB)
        cp_async16(sbase + i * 16, g + i * 4);
    for (int i = (n4 << 2) + tid; i < nf; i += TPB)   // tail (not taken for this n)
        cp_async4(sbase + i * 4, g + i);
}

__global__ void __launch_bounds__(TPB)
lbs_kernel(const float* __restrict__ points,
           const float* __restrict__ weights,
           const float* __restrict__ SE3,
           float* __restrict__ out,
           int n, int ntiles)
{
    extern __shared__ __align__(16) float smem[];
    float*   sw = smem;
    double2* sm = (double2*)(smem + WBUF);   // SE3 rows 0..2 as packed f32x2 pairs

    const int tid = threadIdx.x;

    // --- Startup stagger: de-phase the 7 CTAs co-resident on each SM.
    // Co-resident CTAs have identical bid%148 and distinct bid/148 (grid=148*7),
    // so this spreads their fill/compute phases by ~300ns steps (max 1.8us),
    // breaking the launch-synchronized convoy that leaves DRAM demand gappy.
    {
        unsigned ns = (unsigned)(blockIdx.x / 148) * STAGGER_NS;
        if (ns) __nanosleep(ns);
    }

    // --- Stage SE3 once (rows 0..2 of each joint; each row is one float4) ---
    {
        const float4* g = (const float4*)SE3;
        for (int idx = tid; idx < NJ * 3; idx += TPB) {
            int j = idx / 3;
            int r = idx - j * 3;
            float4 v = g[j * 4 + r];
            *(float4*)(&sm[idx]) = v;
        }
    }

    for (int tile = blockIdx.x; tile < ntiles; tile += GRID) {
        // Issue this tile's smem fill; overlap comes from the 6 other
        // (now phase-staggered) CTAs resident on this SM.
        prefetch_tile(weights, n, tile, sw, tid);
        cp_commit();

        const int base = tile * VPB;
        const int v0 = base + tid;
        const int v1 = base + TPB + tid;
        const bool has0 = (v0 < n);
        const bool has1 = (v1 < n);

        // Point loads fly during the cp.async wait
        float px0 = 0.f, py0 = 0.f, pz0 = 0.f, px1 = 0.f, py1 = 0.f, pz1 = 0.f;
        if (has0) {
            px0 = __ldg(&points[(size_t)v0 * 3 + 0]);
            py0 = __ldg(&points[(size_t)v0 * 3 + 1]);
            pz0 = __ldg(&points[(size_t)v0 * 3 + 2]);
        }
        if (has1) {
            px1 = __ldg(&points[(size_t)v1 * 3 + 0]);
            py1 = __ldg(&points[(size_t)v1 * 3 + 1]);
            pz1 = __ldg(&points[(size_t)v1 * 3 + 2]);
        }

        cp_wait0();
        __syncthreads();   // tile visible to both warps (also orders SE3 staging on iter 0)

        if (has0) {
            // Packed accumulators for blended 3x4 matrices of both vertices
            unsigned long long a0 = 0ull, a1 = 0ull, a2 = 0ull, a3 = 0ull, a4 = 0ull, a5 = 0ull;
            unsigned long long b0 = 0ull, b1 = 0ull, b2 = 0ull, b3 = 0ull, b4 = 0ull, b5 = 0ull;

            const float* wrowA = sw + tid * NJ;          // lane stride 55 words -> conflict-free
            const float* wrowB = sw + (tid + TPB) * NJ;

            #pragma unroll
            for (int j = 0; j < NJ; ++j) {
                float wA = wrowA[j];
                float wB = wrowB[j];
                unsigned long long wA2, wB2;
                asm("mov.b64 %0, {%1, %1};" : "=l"(wA2) : "r"(__float_as_uint(wA)));
                asm("mov.b64 %0, {%1, %1};" : "=l"(wB2) : "r"(__float_as_uint(wB)));

                double2 r0 = sm[j * 3 + 0];   // LDS.128 broadcast, shared by both vertices
                double2 r1 = sm[j * 3 + 1];
                double2 r2 = sm[j * 3 + 2];
                unsigned long long m01 = __double_as_longlong(r0.x);
                unsigned long long m23 = __double_as_longlong(r0.y);
                unsigned long long m45 = __double_as_longlong(r1.x);
                unsigned long long m67 = __double_as_longlong(r1.y);
                unsigned long long m89 = __double_as_longlong(r2.x);
                unsigned long long mAB = __double_as_longlong(r2.y);

                FMA_F32X2(a0, wA2, m01);  FMA_F32X2(b0, wB2, m01);
                FMA_F32X2(a1, wA2, m23);  FMA_F32X2(b1, wB2, m23);
                FMA_F32X2(a2, wA2, m45);  FMA_F32X2(b2, wB2, m45);
                FMA_F32X2(a3, wA2, m67);  FMA_F32X2(b3, wB2, m67);
                FMA_F32X2(a4, wA2, m89);  FMA_F32X2(b4, wB2, m89);
                FMA_F32X2(a5, wA2, mAB);  FMA_F32X2(b5, wB2, mAB);
            }

            // --- Vertex 0 epilogue ---
            {
                float A00, A01, A02, A03, A10, A11, A12, A13, A20, A21, A22, A23;
                asm("mov.b64 {%0, %1}, %2;" : "=f"(A00), "=f"(A01) : "l"(a0));
                asm("mov.b64 {%0, %1}, %2;" : "=f"(A02), "=f"(A03) : "l"(a1));
                asm("mov.b64 {%0, %1}, %2;" : "=f"(A10), "=f"(A11) : "l"(a2));
                asm("mov.b64 {%0, %1}, %2;" : "=f"(A12), "=f"(A13) : "l"(a3));
                asm("mov.b64 {%0, %1}, %2;" : "=f"(A20), "=f"(A21) : "l"(a4));
                asm("mov.b64 {%0, %1}, %2;" : "=f"(A22), "=f"(A23) : "l"(a5));
                out[(size_t)v0 * 3 + 0] = fmaf(A00, px0, fmaf(A01, py0, fmaf(A02, pz0, A03)));
                out[(size_t)v0 * 3 + 1] = fmaf(A10, px0, fmaf(A11, py0, fmaf(A12, pz0, A13)));
                out[(size_t)v0 * 3 + 2] = fmaf(A20, px0, fmaf(A21, py0, fmaf(A22, pz0, A23)));
            }

            // --- Vertex 1 epilogue ---
            if (has1) {
                float A00, A01, A02, A03, A10, A11, A12, A13, A20, A21, A22, A23;
                asm("mov.b64 {%0, %1}, %2;" : "=f"(A00), "=f"(A01) : "l"(b0));
                asm("mov.b64 {%0, %1}, %2;" : "=f"(A02), "=f"(A03) : "l"(b1));
                asm("mov.b64 {%0, %1}, %2;" : "=f"(A10), "=f"(A11) : "l"(b2));
                asm("mov.b64 {%0, %1}, %2;" : "=f"(A12), "=f"(A13) : "l"(b3));
                asm("mov.b64 {%0, %1}, %2;" : "=f"(A20), "=f"(A21) : "l"(b4));
                asm("mov.b64 {%0, %1}, %2;" : "=f"(A22), "=f"(A23) : "l"(b5));
                out[(size_t)v1 * 3 + 0] = fmaf(A00, px1, fmaf(A01, py1, fmaf(A02, pz1, A03)));
                out[(size_t)v1 * 3 + 1] = fmaf(A10, px1, fmaf(A11, py1, fmaf(A12, pz1, A13)));
                out[(size_t)v1 * 3 + 2] = fmaf(A20, px1, fmaf(A21, py1, fmaf(A22, pz1, A23)));
            }
        }

        __syncthreads();   // both warps done reading sw before next iteration overwrites
    }
}

extern "C" void kernel_launch(void* const* d_in, const int* in_sizes, int n_in,
                              void* d_out, int out_size)
{
    const float* points  = (const float*)d_in[0];   // [n,3]
    const float* weights = (const float*)d_in[1];   // [n,55]
    const float* SE3     = (const float*)d_in[2];   // [55,4,4]
    float* out = (float*)d_out;

    int n = in_sizes[0] / 3;
    int ntiles = (n + VPB - 1) / VPB;

    cudaFuncSetAttribute(lbs_kernel, cudaFuncAttributeMaxDynamicSharedMemorySize, SMEM_BYTES);

    int grid = (ntiles < GRID) ? ntiles : GRID;
    lbs_kernel<<<grid, TPB, SMEM_BYTES>>>(points, weights, SE3, out, n, ntiles);
}